// round 5
// baseline (speedup 1.0000x reference)
#include <cuda_runtime.h>
#include <cuda_fp16.h>
#include <cstdint>

// ============================================================================
// Attention: softmax(Q K^T) V, B=4 H=16 S=2048 D=64, fp32 in/out.
// FA2-style kernel on baseline mma.sync (m16n8k16 f16, fp32 accum).
// Precision fix vs R3 (rel_err 1.02e-3): split-fp16 QK^T
//   S = Qhi Khi^T + Qhi Klo^T + Qlo Khi^T   (~fp32-accurate scores)
// Per CTA: 128 Q rows; 8 warps x 16 rows; loop 32 K/V tiles of 64 rows.
// ============================================================================

#define DINLINE __device__ __forceinline__

static constexpr int S_LEN = 2048;
static constexpr int HDIM  = 64;
static constexpr int TM    = 128;          // Q rows per CTA
static constexpr int TN    = 64;           // K/V rows per iteration
static constexpr int NIT   = S_LEN / TN;   // 32
static constexpr int NTHREADS = 256;       // 8 warps

// dynamic SMEM layout (bytes): fp16 tiles, 128 B/row, SW128 swizzled
static constexpr int SM_QH = 0;            // 128 x 64 fp16 (16 KB)
static constexpr int SM_QL = 16384;        // 128 x 64 fp16 (16 KB)
static constexpr int SM_KH = 32768;        // 64 x 64 fp16  ( 8 KB)
static constexpr int SM_KL = 40960;        // 64 x 64 fp16  ( 8 KB)
static constexpr int SM_V  = 49152;        // 64 x 64 fp16  ( 8 KB)
static constexpr int SMEM_BYTES = 57344;   // 56 KB

// ---------------------------------------------------------------------------
DINLINE uint32_t smem_u32(const void* p) {
    uint32_t a;
    asm("{ .reg .u64 t; cvta.to.shared.u64 t, %1; cvt.u32.u64 %0, t; }" : "=r"(a) : "l"(p));
    return a;
}

DINLINE float ex2f(float x) {
    float y;
    asm("ex2.approx.ftz.f32 %0, %1;" : "=f"(y) : "f"(x));
    return y;
}

DINLINE uint32_t h2_bits(__half2 h) {
    uint32_t u;
    __builtin_memcpy(&u, &h, 4);
    return u;
}

// swizzled SMEM address: tile base + SW128(row*128 + colbyte)
DINLINE uint32_t sw_addr(uint32_t base, int row, int colb) {
    uint32_t off = (uint32_t)(row * 128 + colb);
    return base + (off ^ ((off >> 3) & 0x70));
}

DINLINE void ldmatrix_x4(uint32_t* r, uint32_t addr) {
    asm volatile("ldmatrix.sync.aligned.m8n8.x4.shared.b16 {%0,%1,%2,%3}, [%4];"
                 : "=r"(r[0]), "=r"(r[1]), "=r"(r[2]), "=r"(r[3]) : "r"(addr));
}

DINLINE void ldmatrix_x4_trans(uint32_t* r, uint32_t addr) {
    asm volatile("ldmatrix.sync.aligned.m8n8.x4.trans.shared.b16 {%0,%1,%2,%3}, [%4];"
                 : "=r"(r[0]), "=r"(r[1]), "=r"(r[2]), "=r"(r[3]) : "r"(addr));
}

DINLINE void mma_16816(float* c, const uint32_t* a, uint32_t b0, uint32_t b1) {
    asm volatile(
        "mma.sync.aligned.m16n8k16.row.col.f32.f16.f16.f32 "
        "{%0,%1,%2,%3}, {%4,%5,%6,%7}, {%8,%9}, {%0,%1,%2,%3};"
        : "+f"(c[0]), "+f"(c[1]), "+f"(c[2]), "+f"(c[3])
        : "r"(a[0]), "r"(a[1]), "r"(a[2]), "r"(a[3]), "r"(b0), "r"(b1));
}

DINLINE void sts_v2(uint32_t addr, uint32_t x, uint32_t y) {
    asm volatile("st.shared.v2.b32 [%0], {%1, %2};" :: "r"(addr), "r"(x), "r"(y) : "memory");
}

// Split-precision pack: hi = fp16(x), lo = fp16(x - hi)
DINLINE void split2(float x, float y, uint32_t& hi, uint32_t& lo) {
    __half hx = __float2half_rn(x);
    __half hy = __float2half_rn(y);
    __half lx = __float2half_rn(x - __half2float(hx));
    __half ly = __float2half_rn(y - __half2float(hy));
    hi = h2_bits(__halves2half2(hx, hy));
    lo = h2_bits(__halves2half2(lx, ly));
}

// Load nrows x 64 fp32 tile -> hi/lo fp16 SW128 SMEM tiles.
template <int NROWS>
DINLINE void load_tile_split(const float* __restrict__ g, uint32_t shi, uint32_t slo,
                             float scale) {
    const int t = threadIdx.x;
    constexpr int TOT = NROWS * 16;          // float4 count
    constexpr int PER = TOT / NTHREADS;
#pragma unroll
    for (int i = 0; i < PER; i++) {
        int idx = t + i * NTHREADS;
        int row = idx >> 4;
        int c4  = idx & 15;
        float4 v = *reinterpret_cast<const float4*>(g + row * HDIM + c4 * 4);
        uint32_t h0, l0, h1, l1;
        split2(v.x * scale, v.y * scale, h0, l0);
        split2(v.z * scale, v.w * scale, h1, l1);
        sts_v2(sw_addr(shi, row, c4 * 8), h0, h1);
        sts_v2(sw_addr(slo, row, c4 * 8), l0, l1);
    }
}

// Plain fp16 tile load (V)
template <int NROWS>
DINLINE void load_tile(const float* __restrict__ g, uint32_t sbase) {
    const int t = threadIdx.x;
    constexpr int TOT = NROWS * 16;
    constexpr int PER = TOT / NTHREADS;
#pragma unroll
    for (int i = 0; i < PER; i++) {
        int idx = t + i * NTHREADS;
        int row = idx >> 4;
        int c4  = idx & 15;
        float4 v = *reinterpret_cast<const float4*>(g + row * HDIM + c4 * 4);
        __half2 a = __floats2half2_rn(v.x, v.y);
        __half2 b = __floats2half2_rn(v.z, v.w);
        sts_v2(sw_addr(sbase, row, c4 * 8), h2_bits(a), h2_bits(b));
    }
}

// ---------------------------------------------------------------------------
__global__ void __launch_bounds__(NTHREADS, 1)
attn_kernel(const float* __restrict__ Q, const float* __restrict__ K,
            const float* __restrict__ V, float* __restrict__ Out) {
    extern __shared__ char smem[];
    const uint32_t sb = smem_u32(smem);

    const int tid = threadIdx.x;
    const int w   = tid >> 5;
    const int lid = tid & 31;
    const int g   = lid >> 2;     // accum row within 8
    const int tig = lid & 3;      // col pair

    const int bh = blockIdx.x >> 4;
    const int qt = blockIdx.x & 15;
    const size_t head_off = (size_t)bh * S_LEN * HDIM;
    const float* qg = Q + head_off + (size_t)qt * TM * HDIM;
    const float* kg = K + head_off;
    const float* vg = V + head_off;
    float* og = Out + head_off + (size_t)qt * TM * HDIM;

    // ---- stage Q hi/lo (scaled by log2 e so ex2 == exp), build A-frags ----
    load_tile_split<TM>(qg, sb + SM_QH, sb + SM_QL, 1.4426950408889634f);
    __syncthreads();

    uint32_t qh[4][4], ql[4][4];   // [k-block 16][4 regs]
    {
        const int r   = lid & 7;
        const int sel = lid >> 3;
        const int row = 16 * w + (sel & 1) * 8 + r;
#pragma unroll
        for (int kb = 0; kb < 4; kb++) {
            int colb = kb * 32 + (sel >> 1) * 16;
            ldmatrix_x4(qh[kb], sw_addr(sb + SM_QH, row, colb));
            ldmatrix_x4(ql[kb], sw_addr(sb + SM_QL, row, colb));
        }
    }
    __syncthreads();

    float oacc[8][4];
#pragma unroll
    for (int nb = 0; nb < 8; nb++)
#pragma unroll
        for (int i = 0; i < 4; i++) oacc[nb][i] = 0.f;

    float m0 = -__int_as_float(0x7f800000), m1 = m0;
    float l0 = 0.f, l1 = 0.f;

    const int lr   = lid & 7;
    const int lsel = lid >> 3;

    for (int j = 0; j < NIT; j++) {
        // ---- load K_j (split hi/lo), V_j ----
        load_tile_split<TN>(kg + (size_t)j * TN * HDIM, sb + SM_KH, sb + SM_KL, 1.f);
        load_tile<TN>(vg + (size_t)j * TN * HDIM, sb + SM_V);
        __syncthreads();

        // ---- S = Qhi Khi^T + Qhi Klo^T + Qlo Khi^T : 16 x 64 per warp ----
        float sacc[8][4];
#pragma unroll
        for (int nb = 0; nb < 8; nb++) {
#pragma unroll
            for (int i = 0; i < 4; i++) sacc[nb][i] = 0.f;
#pragma unroll
            for (int kbp = 0; kbp < 2; kbp++) {
                uint32_t kh[4], kl[4];
                int colb = 64 * kbp + lsel * 16;
                ldmatrix_x4(kh, sw_addr(sb + SM_KH, 8 * nb + lr, colb));
                ldmatrix_x4(kl, sw_addr(sb + SM_KL, 8 * nb + lr, colb));
                mma_16816(sacc[nb], qh[2 * kbp],     kh[0], kh[1]);
                mma_16816(sacc[nb], qh[2 * kbp + 1], kh[2], kh[3]);
                mma_16816(sacc[nb], ql[2 * kbp],     kh[0], kh[1]);
                mma_16816(sacc[nb], ql[2 * kbp + 1], kh[2], kh[3]);
                mma_16816(sacc[nb], qh[2 * kbp],     kl[0], kl[1]);
                mma_16816(sacc[nb], qh[2 * kbp + 1], kl[2], kl[3]);
            }
        }

        // ---- online softmax (rows g and g+8 of this warp's 16) ----
        float mr0 = sacc[0][0], mr1 = sacc[0][2];
#pragma unroll
        for (int nb = 0; nb < 8; nb++) {
            mr0 = fmaxf(mr0, fmaxf(sacc[nb][0], sacc[nb][1]));
            mr1 = fmaxf(mr1, fmaxf(sacc[nb][2], sacc[nb][3]));
        }
        mr0 = fmaxf(mr0, __shfl_xor_sync(0xffffffffu, mr0, 1));
        mr0 = fmaxf(mr0, __shfl_xor_sync(0xffffffffu, mr0, 2));
        mr1 = fmaxf(mr1, __shfl_xor_sync(0xffffffffu, mr1, 1));
        mr1 = fmaxf(mr1, __shfl_xor_sync(0xffffffffu, mr1, 2));

        float mn0 = fmaxf(m0, mr0), mn1 = fmaxf(m1, mr1);
        float al0 = ex2f(m0 - mn0), al1 = ex2f(m1 - mn1);
        m0 = mn0; m1 = mn1;

        float sum0 = 0.f, sum1 = 0.f;
#pragma unroll
        for (int nb = 0; nb < 8; nb++) {
            sacc[nb][0] = ex2f(sacc[nb][0] - mn0);
            sacc[nb][1] = ex2f(sacc[nb][1] - mn0);
            sacc[nb][2] = ex2f(sacc[nb][2] - mn1);
            sacc[nb][3] = ex2f(sacc[nb][3] - mn1);
            sum0 += sacc[nb][0] + sacc[nb][1];
            sum1 += sacc[nb][2] + sacc[nb][3];
        }
        sum0 += __shfl_xor_sync(0xffffffffu, sum0, 1);
        sum0 += __shfl_xor_sync(0xffffffffu, sum0, 2);
        sum1 += __shfl_xor_sync(0xffffffffu, sum1, 1);
        sum1 += __shfl_xor_sync(0xffffffffu, sum1, 2);
        l0 = l0 * al0 + sum0;
        l1 = l1 * al1 + sum1;

        // rescale O accum
#pragma unroll
        for (int nb = 0; nb < 8; nb++) {
            oacc[nb][0] *= al0; oacc[nb][1] *= al0;
            oacc[nb][2] *= al1; oacc[nb][3] *= al1;
        }

        // pack P into A-fragments
        uint32_t pa[4][4];
#pragma unroll
        for (int kb2 = 0; kb2 < 4; kb2++) {
            pa[kb2][0] = h2_bits(__floats2half2_rn(sacc[2 * kb2][0],     sacc[2 * kb2][1]));
            pa[kb2][1] = h2_bits(__floats2half2_rn(sacc[2 * kb2][2],     sacc[2 * kb2][3]));
            pa[kb2][2] = h2_bits(__floats2half2_rn(sacc[2 * kb2 + 1][0], sacc[2 * kb2 + 1][1]));
            pa[kb2][3] = h2_bits(__floats2half2_rn(sacc[2 * kb2 + 1][2], sacc[2 * kb2 + 1][3]));
        }

        // ---- O += P V : V B-frags via ldmatrix.trans ----
#pragma unroll
        for (int nbp = 0; nbp < 4; nbp++) {
#pragma unroll
            for (int kb2 = 0; kb2 < 4; kb2++) {
                uint32_t vf[4];
                int row  = 16 * kb2 + (lsel & 1) * 8 + lr;
                int colb = 16 * (2 * nbp + (lsel >> 1));
                ldmatrix_x4_trans(vf, sw_addr(sb + SM_V, row, colb));
                mma_16816(oacc[2 * nbp],     pa[kb2], vf[0], vf[1]);
                mma_16816(oacc[2 * nbp + 1], pa[kb2], vf[2], vf[3]);
            }
        }
        __syncthreads();   // before next iteration overwrites K/V
    }

    // ---- epilogue: O / l -> gmem ----
    float inv0 = __fdividef(1.f, l0);
    float inv1 = __fdividef(1.f, l1);
    const int row0 = 16 * w + g;
    const int row1 = row0 + 8;
#pragma unroll
    for (int nb = 0; nb < 8; nb++) {
        int col = 8 * nb + 2 * tig;
        *reinterpret_cast<float2*>(og + (size_t)row0 * HDIM + col) =
            make_float2(oacc[nb][0] * inv0, oacc[nb][1] * inv0);
        *reinterpret_cast<float2*>(og + (size_t)row1 * HDIM + col) =
            make_float2(oacc[nb][2] * inv1, oacc[nb][3] * inv1);
    }
}

// ---------------------------------------------------------------------------
extern "C" void kernel_launch(void* const* d_in, const int* in_sizes, int n_in,
                              void* d_out, int out_size) {
    const float* Q = (const float*)d_in[0];
    const float* K = (const float*)d_in[1];
    const float* V = (const float*)d_in[2];
    float* O = (float*)d_out;

    cudaFuncSetAttribute(attn_kernel, cudaFuncAttributeMaxDynamicSharedMemorySize, SMEM_BYTES);

    dim3 grid(64 * 16);   // (b,h) major; 16 consecutive Q-tile CTAs share K/V in L2
    dim3 block(NTHREADS);
    attn_kernel<<<grid, block, SMEM_BYTES>>>(Q, K, V, O);
}

// round 7
// speedup vs baseline: 1.2072x; 1.2072x over previous
#include <cuda_runtime.h>
#include <cuda_fp16.h>
#include <cstdint>

// ============================================================================
// Attention: softmax(Q K^T) V, B=4 H=16 S=2048 D=64, fp32 in/out.
// FA2-style mma.sync kernel with split-fp16 QK^T (rel_err ~2e-4).
// R5/R6: cp.async double-buffered K/V staging (raw fp32) overlapped with
// MMA+softmax of the previous tile — removes serial DRAM latency per iter.
// (R6 is an infra-failure resubmission of R5, unchanged.)
// ============================================================================

#define DINLINE __device__ __forceinline__

static constexpr int S_LEN = 2048;
static constexpr int HDIM  = 64;
static constexpr int TM    = 128;          // Q rows per CTA
static constexpr int TN    = 64;           // K/V rows per iteration
static constexpr int NIT   = S_LEN / TN;   // 32
static constexpr int NTHREADS = 256;       // 8 warps

// dynamic SMEM layout (bytes)
static constexpr int SM_QH = 0;            // 128 x 64 fp16 SW128 (16 KB)
static constexpr int SM_QL = 16384;        // 128 x 64 fp16 SW128 (16 KB)
static constexpr int SM_KH = 32768;        // 64 x 64 fp16 SW128  ( 8 KB)
static constexpr int SM_KL = 40960;        // 64 x 64 fp16 SW128  ( 8 KB)
static constexpr int SM_V  = 49152;        // 64 x 64 fp16 SW128  ( 8 KB)
static constexpr int SM_ST = 57344;        // fp32 staging: 2 stages x (K 16K + V 16K)
static constexpr int ST_STRIDE = 32768;    // bytes per stage
static constexpr int ST_V_OFF  = 16384;    // V offset within stage
static constexpr int SMEM_BYTES = SM_ST + 2 * ST_STRIDE;   // 120 KB

// ---------------------------------------------------------------------------
DINLINE uint32_t smem_u32(const void* p) {
    uint32_t a;
    asm("{ .reg .u64 t; cvta.to.shared.u64 t, %1; cvt.u32.u64 %0, t; }" : "=r"(a) : "l"(p));
    return a;
}

DINLINE float ex2f(float x) {
    float y;
    asm("ex2.approx.ftz.f32 %0, %1;" : "=f"(y) : "f"(x));
    return y;
}

DINLINE uint32_t h2_bits(__half2 h) {
    uint32_t u;
    __builtin_memcpy(&u, &h, 4);
    return u;
}

// swizzled SMEM address: tile base + SW128(row*128 + colbyte)
DINLINE uint32_t sw_addr(uint32_t base, int row, int colb) {
    uint32_t off = (uint32_t)(row * 128 + colb);
    return base + (off ^ ((off >> 3) & 0x70));
}

DINLINE void ldmatrix_x4(uint32_t* r, uint32_t addr) {
    asm volatile("ldmatrix.sync.aligned.m8n8.x4.shared.b16 {%0,%1,%2,%3}, [%4];"
                 : "=r"(r[0]), "=r"(r[1]), "=r"(r[2]), "=r"(r[3]) : "r"(addr));
}

DINLINE void ldmatrix_x4_trans(uint32_t* r, uint32_t addr) {
    asm volatile("ldmatrix.sync.aligned.m8n8.x4.trans.shared.b16 {%0,%1,%2,%3}, [%4];"
                 : "=r"(r[0]), "=r"(r[1]), "=r"(r[2]), "=r"(r[3]) : "r"(addr));
}

DINLINE void mma_16816(float* c, const uint32_t* a, uint32_t b0, uint32_t b1) {
    asm volatile(
        "mma.sync.aligned.m16n8k16.row.col.f32.f16.f16.f32 "
        "{%0,%1,%2,%3}, {%4,%5,%6,%7}, {%8,%9}, {%0,%1,%2,%3};"
        : "+f"(c[0]), "+f"(c[1]), "+f"(c[2]), "+f"(c[3])
        : "r"(a[0]), "r"(a[1]), "r"(a[2]), "r"(a[3]), "r"(b0), "r"(b1));
}

DINLINE void sts_v2(uint32_t addr, uint32_t x, uint32_t y) {
    asm volatile("st.shared.v2.b32 [%0], {%1, %2};" :: "r"(addr), "r"(x), "r"(y) : "memory");
}

DINLINE float4 lds_v4f(uint32_t addr) {
    float4 v;
    asm volatile("ld.shared.v4.f32 {%0,%1,%2,%3}, [%4];"
                 : "=f"(v.x), "=f"(v.y), "=f"(v.z), "=f"(v.w) : "r"(addr));
    return v;
}

// Split-precision pack: hi = fp16(x), lo = fp16(x - hi)
DINLINE void split2(float x, float y, uint32_t& hi, uint32_t& lo) {
    __half hx = __float2half_rn(x);
    __half hy = __float2half_rn(y);
    __half lx = __float2half_rn(x - __half2float(hx));
    __half ly = __float2half_rn(y - __half2float(hy));
    hi = h2_bits(__halves2half2(hx, hy));
    lo = h2_bits(__halves2half2(lx, ly));
}

// cp.async a 64x64 fp32 tile (16 KB) gmem -> SMEM staging. 4 x 16B per thread.
DINLINE void cp_async_tile(const float* __restrict__ g, uint32_t s) {
    const int t = threadIdx.x;
#pragma unroll
    for (int i = 0; i < 4; i++) {
        int idx = t + i * NTHREADS;               // 16B chunk index
        asm volatile("cp.async.cg.shared.global [%0], [%1], 16;"
                     :: "r"(s + idx * 16), "l"(g + idx * 4) : "memory");
    }
}
#define CP_COMMIT() asm volatile("cp.async.commit_group;" ::: "memory")
#define CP_WAIT0()  asm volatile("cp.async.wait_group 0;" ::: "memory")

// Convert fp32 staging (SMEM) -> split hi/lo fp16 SW128 tiles. 64 rows.
DINLINE void convert_split_64(uint32_t sf32, uint32_t shi, uint32_t slo) {
    const int t = threadIdx.x;
#pragma unroll
    for (int i = 0; i < 4; i++) {
        int idx = t + i * NTHREADS;
        int row = idx >> 4, c4 = idx & 15;
        float4 v = lds_v4f(sf32 + idx * 16);      // own cp.async chunk
        uint32_t h0, l0, h1, l1;
        split2(v.x, v.y, h0, l0);
        split2(v.z, v.w, h1, l1);
        sts_v2(sw_addr(shi, row, c4 * 8), h0, h1);
        sts_v2(sw_addr(slo, row, c4 * 8), l0, l1);
    }
}

// Convert fp32 staging -> plain fp16 SW128 tile (V). 64 rows.
DINLINE void convert_plain_64(uint32_t sf32, uint32_t sbase) {
    const int t = threadIdx.x;
#pragma unroll
    for (int i = 0; i < 4; i++) {
        int idx = t + i * NTHREADS;
        int row = idx >> 4, c4 = idx & 15;
        float4 v = lds_v4f(sf32 + idx * 16);
        __half2 a = __floats2half2_rn(v.x, v.y);
        __half2 b = __floats2half2_rn(v.z, v.w);
        sts_v2(sw_addr(sbase, row, c4 * 8), h2_bits(a), h2_bits(b));
    }
}

// Q: direct gmem load -> split fp16 tiles (runs once, overlapped with cp.async)
DINLINE void load_q_split(const float* __restrict__ g, uint32_t shi, uint32_t slo) {
    const int t = threadIdx.x;
    const float scale = 1.4426950408889634f;   // log2(e)
#pragma unroll
    for (int i = 0; i < 8; i++) {
        int idx = t + i * NTHREADS;
        int row = idx >> 4, c4 = idx & 15;
        float4 v = *reinterpret_cast<const float4*>(g + row * HDIM + c4 * 4);
        uint32_t h0, l0, h1, l1;
        split2(v.x * scale, v.y * scale, h0, l0);
        split2(v.z * scale, v.w * scale, h1, l1);
        sts_v2(sw_addr(shi, row, c4 * 8), h0, h1);
        sts_v2(sw_addr(slo, row, c4 * 8), l0, l1);
    }
}

// ---------------------------------------------------------------------------
__global__ void __launch_bounds__(NTHREADS, 1)
attn_kernel(const float* __restrict__ Q, const float* __restrict__ K,
            const float* __restrict__ V, float* __restrict__ Out) {
    extern __shared__ char smem[];
    const uint32_t sb = smem_u32(smem);

    const int tid = threadIdx.x;
    const int w   = tid >> 5;
    const int lid = tid & 31;
    const int g   = lid >> 2;
    const int tig = lid & 3;

    const int bh = blockIdx.x >> 4;
    const int qt = blockIdx.x & 15;
    const size_t head_off = (size_t)bh * S_LEN * HDIM;
    const float* qg = Q + head_off + (size_t)qt * TM * HDIM;
    const float* kg = K + head_off;
    const float* vg = V + head_off;
    float* og = Out + head_off + (size_t)qt * TM * HDIM;

    // ---- prologue: prefetch K0/V0, stage Q, build Q frags ----
    cp_async_tile(kg, sb + SM_ST);
    cp_async_tile(vg, sb + SM_ST + ST_V_OFF);
    CP_COMMIT();

    load_q_split(qg, sb + SM_QH, sb + SM_QL);
    __syncthreads();

    uint32_t qh[4][4], ql[4][4];
    {
        const int r   = lid & 7;
        const int sel = lid >> 3;
        const int row = 16 * w + (sel & 1) * 8 + r;
#pragma unroll
        for (int kb = 0; kb < 4; kb++) {
            int colb = kb * 32 + (sel >> 1) * 16;
            ldmatrix_x4(qh[kb], sw_addr(sb + SM_QH, row, colb));
            ldmatrix_x4(ql[kb], sw_addr(sb + SM_QL, row, colb));
        }
    }

    float oacc[8][4];
#pragma unroll
    for (int nb = 0; nb < 8; nb++)
#pragma unroll
        for (int i = 0; i < 4; i++) oacc[nb][i] = 0.f;

    float m0 = -__int_as_float(0x7f800000), m1 = m0;
    float l0 = 0.f, l1 = 0.f;

    const int lr   = lid & 7;
    const int lsel = lid >> 3;

    for (int j = 0; j < NIT; j++) {
        const uint32_t st = sb + SM_ST + (j & 1) * ST_STRIDE;

        // ---- wait own cp.async chunks, convert staging -> fp16 tiles ----
        CP_WAIT0();
        convert_split_64(st, sb + SM_KH, sb + SM_KL);
        convert_plain_64(st + ST_V_OFF, sb + SM_V);

        // ---- prefetch tile j+1 (overlaps with MMA/softmax below) ----
        if (j + 1 < NIT) {
            const uint32_t stn = sb + SM_ST + ((j + 1) & 1) * ST_STRIDE;
            cp_async_tile(kg + (size_t)(j + 1) * TN * HDIM, stn);
            cp_async_tile(vg + (size_t)(j + 1) * TN * HDIM, stn + ST_V_OFF);
            CP_COMMIT();
        }
        __syncthreads();   // fp16 tiles visible to all warps

        // ---- S = Qhi Khi^T + Qlo Khi^T + Qhi Klo^T : 16 x 64 per warp ----
        float sacc[8][4];
#pragma unroll
        for (int nb = 0; nb < 8; nb++) {
#pragma unroll
            for (int i = 0; i < 4; i++) sacc[nb][i] = 0.f;
#pragma unroll
            for (int kbp = 0; kbp < 2; kbp++) {
                uint32_t kh[4], kl[4];
                int colb = 64 * kbp + lsel * 16;
                ldmatrix_x4(kh, sw_addr(sb + SM_KH, 8 * nb + lr, colb));
                ldmatrix_x4(kl, sw_addr(sb + SM_KL, 8 * nb + lr, colb));
                mma_16816(sacc[nb], qh[2 * kbp],     kh[0], kh[1]);
                mma_16816(sacc[nb], qh[2 * kbp + 1], kh[2], kh[3]);
                mma_16816(sacc[nb], ql[2 * kbp],     kh[0], kh[1]);
                mma_16816(sacc[nb], ql[2 * kbp + 1], kh[2], kh[3]);
                mma_16816(sacc[nb], qh[2 * kbp],     kl[0], kl[1]);
                mma_16816(sacc[nb], qh[2 * kbp + 1], kl[2], kl[3]);
            }
        }

        // ---- online softmax ----
        float mr0 = sacc[0][0], mr1 = sacc[0][2];
#pragma unroll
        for (int nb = 0; nb < 8; nb++) {
            mr0 = fmaxf(mr0, fmaxf(sacc[nb][0], sacc[nb][1]));
            mr1 = fmaxf(mr1, fmaxf(sacc[nb][2], sacc[nb][3]));
        }
        mr0 = fmaxf(mr0, __shfl_xor_sync(0xffffffffu, mr0, 1));
        mr0 = fmaxf(mr0, __shfl_xor_sync(0xffffffffu, mr0, 2));
        mr1 = fmaxf(mr1, __shfl_xor_sync(0xffffffffu, mr1, 1));
        mr1 = fmaxf(mr1, __shfl_xor_sync(0xffffffffu, mr1, 2));

        float mn0 = fmaxf(m0, mr0), mn1 = fmaxf(m1, mr1);
        float al0 = ex2f(m0 - mn0), al1 = ex2f(m1 - mn1);
        m0 = mn0; m1 = mn1;

        float sum0 = 0.f, sum1 = 0.f;
#pragma unroll
        for (int nb = 0; nb < 8; nb++) {
            sacc[nb][0] = ex2f(sacc[nb][0] - mn0);
            sacc[nb][1] = ex2f(sacc[nb][1] - mn0);
            sacc[nb][2] = ex2f(sacc[nb][2] - mn1);
            sacc[nb][3] = ex2f(sacc[nb][3] - mn1);
            sum0 += sacc[nb][0] + sacc[nb][1];
            sum1 += sacc[nb][2] + sacc[nb][3];
        }
        sum0 += __shfl_xor_sync(0xffffffffu, sum0, 1);
        sum0 += __shfl_xor_sync(0xffffffffu, sum0, 2);
        sum1 += __shfl_xor_sync(0xffffffffu, sum1, 1);
        sum1 += __shfl_xor_sync(0xffffffffu, sum1, 2);
        l0 = l0 * al0 + sum0;
        l1 = l1 * al1 + sum1;

#pragma unroll
        for (int nb = 0; nb < 8; nb++) {
            oacc[nb][0] *= al0; oacc[nb][1] *= al0;
            oacc[nb][2] *= al1; oacc[nb][3] *= al1;
        }

        // pack P into A-fragments
        uint32_t pa[4][4];
#pragma unroll
        for (int kb2 = 0; kb2 < 4; kb2++) {
            pa[kb2][0] = h2_bits(__floats2half2_rn(sacc[2 * kb2][0],     sacc[2 * kb2][1]));
            pa[kb2][1] = h2_bits(__floats2half2_rn(sacc[2 * kb2][2],     sacc[2 * kb2][3]));
            pa[kb2][2] = h2_bits(__floats2half2_rn(sacc[2 * kb2 + 1][0], sacc[2 * kb2 + 1][1]));
            pa[kb2][3] = h2_bits(__floats2half2_rn(sacc[2 * kb2 + 1][2], sacc[2 * kb2 + 1][3]));
        }

        // ---- O += P V ----
#pragma unroll
        for (int nbp = 0; nbp < 4; nbp++) {
#pragma unroll
            for (int kb2 = 0; kb2 < 4; kb2++) {
                uint32_t vf[4];
                int row  = 16 * kb2 + (lsel & 1) * 8 + lr;
                int colb = 16 * (2 * nbp + (lsel >> 1));
                ldmatrix_x4_trans(vf, sw_addr(sb + SM_V, row, colb));
                mma_16816(oacc[2 * nbp],     pa[kb2], vf[0], vf[1]);
                mma_16816(oacc[2 * nbp + 1], pa[kb2], vf[2], vf[3]);
            }
        }
        __syncthreads();   // fp16 tiles consumed; next iter may overwrite
    }

    // ---- epilogue: O / l -> gmem ----
    float inv0 = __fdividef(1.f, l0);
    float inv1 = __fdividef(1.f, l1);
    const int row0 = 16 * w + g;
    const int row1 = row0 + 8;
#pragma unroll
    for (int nb = 0; nb < 8; nb++) {
        int col = 8 * nb + 2 * tig;
        *reinterpret_cast<float2*>(og + (size_t)row0 * HDIM + col) =
            make_float2(oacc[nb][0] * inv0, oacc[nb][1] * inv0);
        *reinterpret_cast<float2*>(og + (size_t)row1 * HDIM + col) =
            make_float2(oacc[nb][2] * inv1, oacc[nb][3] * inv1);
    }
}

// ---------------------------------------------------------------------------
extern "C" void kernel_launch(void* const* d_in, const int* in_sizes, int n_in,
                              void* d_out, int out_size) {
    const float* Q = (const float*)d_in[0];
    const float* K = (const float*)d_in[1];
    const float* V = (const float*)d_in[2];
    float* O = (float*)d_out;

    cudaFuncSetAttribute(attn_kernel, cudaFuncAttributeMaxDynamicSharedMemorySize, SMEM_BYTES);

    dim3 grid(64 * 16);   // (b,h) major; 16 consecutive Q-tile CTAs share K/V in L2
    dim3 block(NTHREADS);
    attn_kernel<<<grid, block, SMEM_BYTES>>>(Q, K, V, O);
}